// round 5
// baseline (speedup 1.0000x reference)
#include <cuda_runtime.h>
#include <cuda_bf16.h>
#include <cstdint>

#define T_STEPS 2048
#define B_SZ    32
#define D_SZ    512
#define H_SZ    512
#define G_SZ    2048
#define NBLK    128

// ---------------- device scratch ----------------
__device__ float g_xproj[(size_t)T_STEPS * G_SZ * B_SZ];   // [T][4H][B]
__device__ float g_m[2][H_SZ * B_SZ];                      // [h][b]
__device__ int   g_barA;    // arrivals from blocks 0..63   (m rows 0..255)
__device__ int   g_barB;    // arrivals from blocks 64..127 (m rows 256..511)

// ---------------- helpers ----------------
#define CP_ASYNC16(dst_u32, src_ptr) \
    asm volatile("cp.async.cg.shared.global [%0], [%1], 16;\n" :: "r"(dst_u32), "l"(src_ptr))
#define CP_COMMIT() asm volatile("cp.async.commit_group;\n")
#define CP_WAIT(N)  asm volatile("cp.async.wait_group %0;\n" :: "n"(N))

__device__ __forceinline__ void split_tf(float x, uint32_t& hi, uint32_t& lo) {
    uint32_t h = __float_as_uint(x) & 0xffffe000u;
    hi = h;
    lo = __float_as_uint(x - __uint_as_float(h));
}
__device__ __forceinline__ void mma_tf32(float& d0, float& d1, float& d2, float& d3,
                                         uint32_t a0, uint32_t a1, uint32_t a2, uint32_t a3,
                                         uint32_t b0, uint32_t b1) {
    asm volatile(
        "mma.sync.aligned.m16n8k8.row.col.f32.tf32.tf32.f32 "
        "{%0,%1,%2,%3},{%4,%5,%6,%7},{%8,%9},{%0,%1,%2,%3};"
        : "+f"(d0), "+f"(d1), "+f"(d2), "+f"(d3)
        : "r"(a0), "r"(a1), "r"(a2), "r"(a3), "r"(b0), "r"(b1));
}

// ============ phase 1: x_proj GEMM (3xTF32, 3-stage pipeline) ============
#define XPA 2304   // 64*36 floats per A buffer
#define XPB 4352   // 32*136 floats per B buffer
#define XP_SMEM_FL (3 * (XPA + XPB))

__global__ __launch_bounds__(256, 2) void xproj_gemm(
    const float* __restrict__ A, const float* __restrict__ Bm,
    const float* __restrict__ bias)
{
    extern __shared__ float sm[];
    float* As = sm;                // 3 * 2304
    float* Bs = sm + 3 * XPA;      // 3 * 4352
    float* stage = Bs;             // epilogue overlay (needs 128*68 = 8704 <= 13056)

    const unsigned as_u32 = (unsigned)__cvta_generic_to_shared(As);
    const unsigned bs_u32 = (unsigned)__cvta_generic_to_shared(Bs);

    const int tid = threadIdx.x;

    if (blockIdx.x == 0 && blockIdx.y == 0) {   // fold reset
        if (tid == 0) { g_barA = 0; g_barB = 0; }
        for (int i = tid; i < H_SZ * B_SZ; i += 256) g_m[0][i] = 0.0f;
    }

    const int n0 = blockIdx.x * 128;
    const int m0 = blockIdx.y * 64;
    const int w   = tid >> 5;
    const int l   = tid & 31;
    const int gid = l >> 2;
    const int tig = l & 3;
    const int nw  = w * 16;

    auto issue = [&](int it, int buf) {
        const int kc = it * 32;
#pragma unroll
        for (int i = 0; i < 2; i++) {
            int idx = tid + i * 256;
            int m = idx >> 3, kq = (idx & 7) << 2;
            CP_ASYNC16(as_u32 + (unsigned)((buf * XPA + m * 36 + kq) * 4),
                       A + (size_t)(m0 + m) * D_SZ + kc + kq);
        }
#pragma unroll
        for (int i = 0; i < 4; i++) {
            int idx = tid + i * 256;
            int k = idx >> 5, nq = (idx & 31) << 2;
            CP_ASYNC16(bs_u32 + (unsigned)((buf * XPB + k * 136 + nq) * 4),
                       Bm + (size_t)(kc + k) * G_SZ + n0 + nq);
        }
        CP_COMMIT();
    };

    float acc1[4][2][4], acc2[4][2][4];
#pragma unroll
    for (int mt = 0; mt < 4; mt++)
#pragma unroll
        for (int nt = 0; nt < 2; nt++)
#pragma unroll
            for (int r = 0; r < 4; r++) { acc1[mt][nt][r] = 0.0f; acc2[mt][nt][r] = 0.0f; }

    issue(0, 0);
    issue(1, 1);

#pragma unroll 1
    for (int it = 0; it < 16; it++) {
        if (it < 15) { CP_WAIT(1); } else { CP_WAIT(0); }
        __syncthreads();
        if (it + 2 < 16) issue(it + 2, (it + 2) % 3);

        const float* Ab = As + (it % 3) * XPA;
        const float* Bb = Bs + (it % 3) * XPB;

#pragma unroll
        for (int kt = 0; kt < 4; kt++) {
            uint32_t bh[2][2], bl[2][2];
#pragma unroll
            for (int nt = 0; nt < 2; nt++) {
                float w0 = Bb[(kt * 8 + tig) * 136 + nw + nt * 8 + gid];
                float w1 = Bb[(kt * 8 + tig + 4) * 136 + nw + nt * 8 + gid];
                split_tf(w0, bh[nt][0], bl[nt][0]);
                split_tf(w1, bh[nt][1], bl[nt][1]);
            }
#pragma unroll
            for (int mt = 0; mt < 4; mt++) {
                float x0 = Ab[(mt * 16 + gid) * 36 + kt * 8 + tig];
                float x1 = Ab[(mt * 16 + gid + 8) * 36 + kt * 8 + tig];
                float x2 = Ab[(mt * 16 + gid) * 36 + kt * 8 + tig + 4];
                float x3 = Ab[(mt * 16 + gid + 8) * 36 + kt * 8 + tig + 4];
                uint32_t ah0, al0, ah1, al1, ah2, al2, ah3, al3;
                split_tf(x0, ah0, al0); split_tf(x1, ah1, al1);
                split_tf(x2, ah2, al2); split_tf(x3, ah3, al3);
#pragma unroll
                for (int nt = 0; nt < 2; nt++) {
                    mma_tf32(acc1[mt][nt][0], acc1[mt][nt][1], acc1[mt][nt][2], acc1[mt][nt][3],
                             ah0, ah1, ah2, ah3, bh[nt][0], bh[nt][1]);
                    mma_tf32(acc2[mt][nt][0], acc2[mt][nt][1], acc2[mt][nt][2], acc2[mt][nt][3],
                             ah0, ah1, ah2, ah3, bl[nt][0], bl[nt][1]);
                    mma_tf32(acc2[mt][nt][0], acc2[mt][nt][1], acc2[mt][nt][2], acc2[mt][nt][3],
                             al0, al1, al2, al3, bh[nt][0], bh[nt][1]);
                }
            }
        }
    }
    __syncthreads();   // protect stage overlay (Bs) against last compute reads

#pragma unroll
    for (int mt = 0; mt < 4; mt++)
#pragma unroll
        for (int nt = 0; nt < 2; nt++) {
            int m = mt * 16 + gid;
            int n = nw + nt * 8 + tig * 2;
            stage[n * 68 + m]           = acc1[mt][nt][0] + acc2[mt][nt][0];
            stage[(n + 1) * 68 + m]     = acc1[mt][nt][1] + acc2[mt][nt][1];
            stage[n * 68 + m + 8]       = acc1[mt][nt][2] + acc2[mt][nt][2];
            stage[(n + 1) * 68 + m + 8] = acc1[mt][nt][3] + acc2[mt][nt][3];
        }
    __syncthreads();

#pragma unroll
    for (int i = 0; i < 8; i++) {
        int idx = tid + i * 256;
        int n = idx >> 4, mq = (idx & 15) << 2;
        float4 v = *(float4*)&stage[n * 68 + mq];
        float bb = bias[n0 + n];
        v.x += bb; v.y += bb; v.z += bb; v.w += bb;
        int mg = m0 + mq;
        int t = mg >> 5, b = mg & 31;
        *(float4*)&g_xproj[((size_t)t * G_SZ + n0 + n) * B_SZ + b] = v;
    }
}

// ============ phase 2: persistent recurrence ============
// 128 blocks x 512 threads. Block owns 4 h (16 gate cols).
// Warps: wk = w&7 (K-split 8), grp = w>>3 (cc group of 8).
#define MS 40
#define RED_OFF (H_SZ * MS)            // 20480
#define XP_OFF  (RED_OFF + 16 * 288)   // red: [16w][8cc][36]
#define PAD_OFF (XP_OFF + 2 * 512)
#define SMEM_FLOATS_L (PAD_OFF + 2 * 32)

__device__ __forceinline__ float fsig(float x)  { return 1.0f / (1.0f + __expf(-x)); }
__device__ __forceinline__ float ftanh(float x) { return 1.0f - 2.0f / (__expf(2.0f * x) + 1.0f); }

__global__ __launch_bounds__(512, 1) void lstm_kernel(
    const float* __restrict__ paddings,
    const float* __restrict__ W_h,
    float* __restrict__ out,
    int write_final)
{
    extern __shared__ float smem[];
    float* m_s   = smem;
    float* red   = smem + RED_OFF;
    float* xp_s  = smem + XP_OFF;     // [2][16cc][32b]
    float* pad_s = smem + PAD_OFF;    // [2][32]

    const unsigned ms_u32  = (unsigned)__cvta_generic_to_shared(m_s);
    const unsigned xp_u32  = (unsigned)__cvta_generic_to_shared(xp_s);
    const unsigned pad_u32 = (unsigned)__cvta_generic_to_shared(pad_s);

    const int tid = threadIdx.x;
    const int bid = blockIdx.x;
    const int h_base = bid * 4;

    const int l   = tid & 31;
    const int w   = tid >> 5;
    const int gid = l >> 2;
    const int tig = l & 3;
    const int wk  = w & 7;      // K-split index
    const int grp = w >> 3;     // cc-group (0: cc 0-7, 1: cc 8-15)

    // W fragments: warp covers k = j*64 + wk*8 .. +8, cc = grp*8 + gid
    uint32_t Whi[8][2], Wlo[8][2];
    {
        const int cc = grp * 8 + gid;
        const int g  = cc & 3;
        const int j4 = cc >> 2;
        const float* wp = W_h + (size_t)g * H_SZ + h_base + j4;
#pragma unroll
        for (int j = 0; j < 8; j++)
#pragma unroll
            for (int r = 0; r < 2; r++) {
                int k = j * 64 + wk * 8 + tig + r * 4;
                split_tf(wp[(size_t)k * G_SZ], Whi[j][r], Wlo[j][r]);
            }
    }

    // cell ownership (tid<128)
    const int cb  = tid & 31;
    const int cj  = tid >> 5;
    const int h_o = h_base + cj;

    // xp loader coords (tid<128)
    const int xp_cc = tid >> 3;
    const int xp_q  = (tid & 7) << 2;
    const float* xp_src_base = g_xproj +
        ((size_t)((xp_cc & 3) * H_SZ + h_base + (xp_cc >> 2))) * B_SZ + xp_q;

    // prologue: xp(0) + pad(0)
    if (tid < 128)
        CP_ASYNC16(xp_u32 + (unsigned)((xp_cc * B_SZ + xp_q) * 4), xp_src_base);
    if (tid >= 128 && tid < 136)
        CP_ASYNC16(pad_u32 + (unsigned)((tid - 128) * 16), paddings + (tid - 128) * 4);
    CP_COMMIT();

    float c_reg = 0.0f;

#pragma unroll 1
    for (int s = 0; s < T_STEPS; s++) {
        const float* msrc = g_m[s & 1];
        const int pb = s & 1, nb = pb ^ 1;

        // ---- wait group A (m rows 0..255 published), then load them ----
        if (tid == 480 && s) {
            while (*(volatile int*)&g_barA < 64 * s) { }
            __threadfence();
        }
        __syncthreads();
#pragma unroll
        for (int li = 0; li < 4; li++) {
            int idx = tid + li * 512;
            int k = idx >> 3, q = (idx & 7) << 2;
            CP_ASYNC16(ms_u32 + (unsigned)((k * MS + q) * 4), msrc + k * B_SZ + q);
        }
        CP_COMMIT();   // G1

        // ---- wait group B (rows 256..511) while G1 flies ----
        if (tid == 480 && s) {
            while (*(volatile int*)&g_barB < 64 * s) { }
            __threadfence();
        }
        __syncthreads();
#pragma unroll
        for (int li = 4; li < 8; li++) {
            int idx = tid + li * 512;
            int k = idx >> 3, q = (idx & 7) << 2;
            CP_ASYNC16(ms_u32 + (unsigned)((k * MS + q) * 4), msrc + k * B_SZ + q);
        }
        CP_COMMIT();   // G2

        // G3: prefetch xp(s+1) + pad(s+1)
        if (s + 1 < T_STEPS) {
            if (tid < 128)
                CP_ASYNC16(xp_u32 + (unsigned)(((nb * 512) + xp_cc * B_SZ + xp_q) * 4),
                           xp_src_base + (size_t)(s + 1) * G_SZ * B_SZ);
            if (tid >= 128 && tid < 136)
                CP_ASYNC16(pad_u32 + (unsigned)((nb * 32 + (tid - 128) * 4) * 4),
                           paddings + (size_t)(s + 1) * B_SZ + (tid - 128) * 4);
        }
        CP_COMMIT();   // G3

        float acc1[2][4], acc2[2][4];
#pragma unroll
        for (int mt = 0; mt < 2; mt++)
#pragma unroll
            for (int r = 0; r < 4; r++) { acc1[mt][r] = 0.0f; acc2[mt][r] = 0.0f; }

        CP_WAIT(2);   // G1 (and previous G3) done
        __syncthreads();

#pragma unroll
        for (int j = 0; j < 8; j++) {
            if (j == 4) { CP_WAIT(1); __syncthreads(); }   // G2 done
            const int kb = j * 64 + wk * 8 + tig;
            const float* mp0 = &m_s[kb * MS];
            const float* mp4 = &m_s[(kb + 4) * MS];
#pragma unroll
            for (int mt = 0; mt < 2; mt++) {
                const int b = mt * 16 + gid;
                float x0 = mp0[b], x1 = mp0[b + 8];
                float x2 = mp4[b], x3 = mp4[b + 8];
                uint32_t ah0, al0, ah1, al1, ah2, al2, ah3, al3;
                split_tf(x0, ah0, al0); split_tf(x1, ah1, al1);
                split_tf(x2, ah2, al2); split_tf(x3, ah3, al3);
                mma_tf32(acc1[mt][0], acc1[mt][1], acc1[mt][2], acc1[mt][3],
                         ah0, ah1, ah2, ah3, Whi[j][0], Whi[j][1]);
                mma_tf32(acc2[mt][0], acc2[mt][1], acc2[mt][2], acc2[mt][3],
                         ah0, ah1, ah2, ah3, Wlo[j][0], Wlo[j][1]);
                mma_tf32(acc2[mt][0], acc2[mt][1], acc2[mt][2], acc2[mt][3],
                         al0, al1, al2, al3, Whi[j][0], Whi[j][1]);
            }
        }

        // partials -> red[w][cc_loc][36]
        {
            float* rp = red + w * 288;
            const int cc = tig * 2;
#pragma unroll
            for (int mt = 0; mt < 2; mt++) {
                const int b = mt * 16 + gid;
                rp[cc * 36 + b]           = acc1[mt][0] + acc2[mt][0];
                rp[(cc + 1) * 36 + b]     = acc1[mt][1] + acc2[mt][1];
                rp[cc * 36 + b + 8]       = acc1[mt][2] + acc2[mt][2];
                rp[(cc + 1) * 36 + b + 8] = acc1[mt][3] + acc2[mt][3];
            }
        }
        __syncthreads();

        // cell update: direct 8-deep reduction per gate (tid < 128)
        float m2 = 0.0f, c2 = 0.0f;
        if (tid < 128) {
            float gate[4];
#pragma unroll
            for (int g = 0; g < 4; g++) {
                const int cc  = cj * 4 + g;
                const float* rb = red + ((cc >> 3) * 8) * 288 + (cc & 7) * 36 + cb;
                float sum = xp_s[pb * 512 + cc * 32 + cb];
#pragma unroll
                for (int ww = 0; ww < 8; ww++) sum += rb[ww * 288];
                gate[g] = sum;
            }
            float p     = pad_s[pb * 32 + cb];
            float mprev = m_s[h_o * MS + cb];

            float ii = fsig(gate[0]), ff = fsig(gate[1]);
            float gg = ftanh(gate[2]), oo = fsig(gate[3]);
            float cn = ff * c_reg + ii * gg;
            float mn = oo * ftanh(cn);
            m2 = mn + (mprev - mn) * p;
            c2 = cn + (c_reg - cn) * p;
            c_reg = c2;
            g_m[(s + 1) & 1][h_o * B_SZ + cb] = m2;
        }

        __syncthreads();
        if (tid == 480) {
            __threadfence();
            atomicAdd((bid < 64) ? &g_barA : &g_barB, 1);
        }
        if (tid < 128) {
            out[((size_t)s * B_SZ + cb) * H_SZ + h_o] = m2;
            if (write_final && s == T_STEPS - 1) {
                size_t base = (size_t)T_STEPS * B_SZ * H_SZ;
                out[base + (size_t)cb * H_SZ + h_o] = m2;
                out[base + (size_t)B_SZ * H_SZ + (size_t)cb * H_SZ + h_o] = c2;
            }
        }
    }
}

// ---------------- launch ----------------
extern "C" void kernel_launch(void* const* d_in, const int* in_sizes, int n_in,
                              void* d_out, int out_size)
{
    const float* input = (const float*)d_in[0];
    const float* padd  = (const float*)d_in[1];
    const float* W_x   = (const float*)d_in[2];
    const float* W_h   = (const float*)d_in[3];
    const float* bias  = (const float*)d_in[4];
    float* out = (float*)d_out;

    const size_t xp_smem = (size_t)XP_SMEM_FL * sizeof(float);
    const size_t ls_smem = (size_t)SMEM_FLOATS_L * sizeof(float);
    cudaFuncSetAttribute(xproj_gemm, cudaFuncAttributeMaxDynamicSharedMemorySize, (int)xp_smem);
    cudaFuncSetAttribute(lstm_kernel, cudaFuncAttributeMaxDynamicSharedMemorySize, (int)ls_smem);

    int write_final =
        ((size_t)out_size >= (size_t)T_STEPS * B_SZ * H_SZ + 2u * B_SZ * H_SZ) ? 1 : 0;

    xproj_gemm<<<dim3(G_SZ / 128, (T_STEPS * B_SZ) / 64), 256, xp_smem>>>(input, W_x, bias);
    lstm_kernel<<<NBLK, 512, ls_smem>>>(padd, W_h, out, write_final);
}

// round 7
// speedup vs baseline: 1.1570x; 1.1570x over previous
#include <cuda_runtime.h>
#include <cuda_bf16.h>
#include <cstdint>

#define T_STEPS 2048
#define B_SZ    32
#define D_SZ    512
#define H_SZ    512
#define G_SZ    2048
#define NBLK    128

// ---------------- device scratch ----------------
__device__ float g_xproj[(size_t)T_STEPS * G_SZ * B_SZ];   // [T][4H][B]
__device__ float g_m[2][H_SZ * B_SZ];                      // [h][b]
__device__ int   g_bar;

// ---------------- helpers ----------------
#define CP_ASYNC16(dst_u32, src_ptr) \
    asm volatile("cp.async.cg.shared.global [%0], [%1], 16;\n" :: "r"(dst_u32), "l"(src_ptr))
#define CP_COMMIT() asm volatile("cp.async.commit_group;\n")
#define CP_WAIT(N)  asm volatile("cp.async.wait_group %0;\n" :: "n"(N))

__device__ __forceinline__ void split_tf(float x, uint32_t& hi, uint32_t& lo) {
    uint32_t h = __float_as_uint(x) & 0xffffe000u;
    hi = h;
    lo = __float_as_uint(x - __uint_as_float(h));
}
__device__ __forceinline__ void mma_tf32(float& d0, float& d1, float& d2, float& d3,
                                         uint32_t a0, uint32_t a1, uint32_t a2, uint32_t a3,
                                         uint32_t b0, uint32_t b1) {
    asm volatile(
        "mma.sync.aligned.m16n8k8.row.col.f32.tf32.tf32.f32 "
        "{%0,%1,%2,%3},{%4,%5,%6,%7},{%8,%9},{%0,%1,%2,%3};"
        : "+f"(d0), "+f"(d1), "+f"(d2), "+f"(d3)
        : "r"(a0), "r"(a1), "r"(a2), "r"(a3), "r"(b0), "r"(b1));
}

// ============ phase 1: x_proj GEMM (3xTF32, 3-stage pipeline) ============
#define XPA 2304   // 64*36 floats per A buffer
#define XPB 4352   // 32*136 floats per B buffer
#define XP_SMEM_FL (3 * (XPA + XPB))

__global__ __launch_bounds__(256, 2) void xproj_gemm(
    const float* __restrict__ A, const float* __restrict__ Bm,
    const float* __restrict__ bias)
{
    extern __shared__ float sm[];
    float* As = sm;
    float* Bs = sm + 3 * XPA;
    float* stage = Bs;             // epilogue overlay (128*68 = 8704 <= 13056)

    const unsigned as_u32 = (unsigned)__cvta_generic_to_shared(As);
    const unsigned bs_u32 = (unsigned)__cvta_generic_to_shared(Bs);

    const int tid = threadIdx.x;

    if (blockIdx.x == 0 && blockIdx.y == 0) {   // fold reset
        if (tid == 0) g_bar = 0;
        for (int i = tid; i < H_SZ * B_SZ; i += 256) g_m[0][i] = 0.0f;
    }

    const int n0 = blockIdx.x * 128;
    const int m0 = blockIdx.y * 64;
    const int w   = tid >> 5;
    const int l   = tid & 31;
    const int gid = l >> 2;
    const int tig = l & 3;
    const int nw  = w * 16;

    auto issue = [&](int it, int buf) {
        const int kc = it * 32;
#pragma unroll
        for (int i = 0; i < 2; i++) {
            int idx = tid + i * 256;
            int m = idx >> 3, kq = (idx & 7) << 2;
            CP_ASYNC16(as_u32 + (unsigned)((buf * XPA + m * 36 + kq) * 4),
                       A + (size_t)(m0 + m) * D_SZ + kc + kq);
        }
#pragma unroll
        for (int i = 0; i < 4; i++) {
            int idx = tid + i * 256;
            int k = idx >> 5, nq = (idx & 31) << 2;
            CP_ASYNC16(bs_u32 + (unsigned)((buf * XPB + k * 136 + nq) * 4),
                       Bm + (size_t)(kc + k) * G_SZ + n0 + nq);
        }
        CP_COMMIT();
    };

    float acc1[4][2][4], acc2[4][2][4];
#pragma unroll
    for (int mt = 0; mt < 4; mt++)
#pragma unroll
        for (int nt = 0; nt < 2; nt++)
#pragma unroll
            for (int r = 0; r < 4; r++) { acc1[mt][nt][r] = 0.0f; acc2[mt][nt][r] = 0.0f; }

    issue(0, 0);
    issue(1, 1);

#pragma unroll 1
    for (int it = 0; it < 16; it++) {
        if (it < 15) { CP_WAIT(1); } else { CP_WAIT(0); }
        __syncthreads();
        if (it + 2 < 16) issue(it + 2, (it + 2) % 3);

        const float* Ab = As + (it % 3) * XPA;
        const float* Bb = Bs + (it % 3) * XPB;

#pragma unroll
        for (int kt = 0; kt < 4; kt++) {
            uint32_t bh[2][2], bl[2][2];
#pragma unroll
            for (int nt = 0; nt < 2; nt++) {
                float w0 = Bb[(kt * 8 + tig) * 136 + nw + nt * 8 + gid];
                float w1 = Bb[(kt * 8 + tig + 4) * 136 + nw + nt * 8 + gid];
                split_tf(w0, bh[nt][0], bl[nt][0]);
                split_tf(w1, bh[nt][1], bl[nt][1]);
            }
#pragma unroll
            for (int mt = 0; mt < 4; mt++) {
                float x0 = Ab[(mt * 16 + gid) * 36 + kt * 8 + tig];
                float x1 = Ab[(mt * 16 + gid + 8) * 36 + kt * 8 + tig];
                float x2 = Ab[(mt * 16 + gid) * 36 + kt * 8 + tig + 4];
                float x3 = Ab[(mt * 16 + gid + 8) * 36 + kt * 8 + tig + 4];
                uint32_t ah0, al0, ah1, al1, ah2, al2, ah3, al3;
                split_tf(x0, ah0, al0); split_tf(x1, ah1, al1);
                split_tf(x2, ah2, al2); split_tf(x3, ah3, al3);
#pragma unroll
                for (int nt = 0; nt < 2; nt++) {
                    mma_tf32(acc1[mt][nt][0], acc1[mt][nt][1], acc1[mt][nt][2], acc1[mt][nt][3],
                             ah0, ah1, ah2, ah3, bh[nt][0], bh[nt][1]);
                    mma_tf32(acc2[mt][nt][0], acc2[mt][nt][1], acc2[mt][nt][2], acc2[mt][nt][3],
                             ah0, ah1, ah2, ah3, bl[nt][0], bl[nt][1]);
                    mma_tf32(acc2[mt][nt][0], acc2[mt][nt][1], acc2[mt][nt][2], acc2[mt][nt][3],
                             al0, al1, al2, al3, bh[nt][0], bh[nt][1]);
                }
            }
        }
    }
    __syncthreads();

#pragma unroll
    for (int mt = 0; mt < 4; mt++)
#pragma unroll
        for (int nt = 0; nt < 2; nt++) {
            int m = mt * 16 + gid;
            int n = nw + nt * 8 + tig * 2;
            stage[n * 68 + m]           = acc1[mt][nt][0] + acc2[mt][nt][0];
            stage[(n + 1) * 68 + m]     = acc1[mt][nt][1] + acc2[mt][nt][1];
            stage[n * 68 + m + 8]       = acc1[mt][nt][2] + acc2[mt][nt][2];
            stage[(n + 1) * 68 + m + 8] = acc1[mt][nt][3] + acc2[mt][nt][3];
        }
    __syncthreads();

#pragma unroll
    for (int i = 0; i < 8; i++) {
        int idx = tid + i * 256;
        int n = idx >> 4, mq = (idx & 15) << 2;
        float4 v = *(float4*)&stage[n * 68 + mq];
        float bb = bias[n0 + n];
        v.x += bb; v.y += bb; v.z += bb; v.w += bb;
        int mg = m0 + mq;
        int t = mg >> 5, b = mg & 31;
        *(float4*)&g_xproj[((size_t)t * G_SZ + n0 + n) * B_SZ + b] = v;
    }
}

// ============ phase 2: persistent recurrence ============
// 128 blocks x 512 threads. K-split 16; warp-private cp.async m pipeline.
#define MS 40
#define RED_OFF   (H_SZ * MS)                 // 20480
#define GSUM_OFF  (RED_OFF + 16 * 576)        // red [16w][16cc][36]
#define XP_OFF    (GSUM_OFF + 512)
#define PAD_OFF   (XP_OFF + 2 * 512)
#define SMEM_FLOATS_L (PAD_OFF + 2 * 32)

__device__ __forceinline__ float fsig(float x)  { return 1.0f / (1.0f + __expf(-x)); }
__device__ __forceinline__ float ftanh(float x) { return 1.0f - 2.0f / (__expf(2.0f * x) + 1.0f); }

__global__ __launch_bounds__(512, 1) void lstm_kernel(
    const float* __restrict__ paddings,
    const float* __restrict__ W_h,
    float* __restrict__ out,
    int write_final)
{
    extern __shared__ float smem[];
    float* m_s   = smem;              // [512][40]
    float* red   = smem + RED_OFF;    // [16w][16cc][36]
    float* gsum  = smem + GSUM_OFF;   // [512]
    float* xp_s  = smem + XP_OFF;     // [2][16cc][32b]
    float* pad_s = smem + PAD_OFF;    // [2][32]

    const unsigned ms_u32  = (unsigned)__cvta_generic_to_shared(m_s);
    const unsigned xp_u32  = (unsigned)__cvta_generic_to_shared(xp_s);
    const unsigned pad_u32 = (unsigned)__cvta_generic_to_shared(pad_s);

    const int tid = threadIdx.x;
    const int bid = blockIdx.x;
    const int h_base = bid * 4;

    const int l   = tid & 31;
    const int w   = tid >> 5;      // K-split 16
    const int gid = l >> 2;
    const int tig = l & 3;

    // W fragments: warp w owns k rows {j*128 + w*8 .. +8}, all 16 cc
    uint32_t Whi[4][2][2], Wlo[4][2][2];
#pragma unroll
    for (int j = 0; j < 4; j++)
#pragma unroll
        for (int nt = 0; nt < 2; nt++)
#pragma unroll
            for (int r = 0; r < 2; r++) {
                int k  = j * 128 + w * 8 + tig + r * 4;
                int cc = nt * 8 + gid;
                int g  = cc & 3;
                int j4 = cc >> 2;
                float wv = W_h[(size_t)k * G_SZ + g * H_SZ + h_base + j4];
                split_tf(wv, Whi[j][nt][r], Wlo[j][nt][r]);
            }

    // cell ownership (tid<128): b=tid&31, j=tid>>5
    const int cb  = tid & 31;
    const int cj  = tid >> 5;
    const int h_o = h_base + cj;

    // xp loader coords (tid<128)
    const int xp_cc = tid >> 3;
    const int xp_q  = (tid & 7) << 2;
    const float* xp_src_base = g_xproj +
        ((size_t)((xp_cc & 3) * H_SZ + h_base + (xp_cc >> 2))) * B_SZ + xp_q;

    // warp-private m loader: lane l -> row w*8 + (l>>2), quads (l&3)*4 and (l&3)*4+16
    // (4 lanes/row x 2 float4 = 8 float4 = full 32-float row)  [R6 bug: only 1 quad]
    const int m_row = w * 8 + (l >> 2);
    const int m_q   = (l & 3) << 2;

    // prologue group: xp(0) + pad(0) (uniform group count across threads)
    if (tid < 128)
        CP_ASYNC16(xp_u32 + (unsigned)((xp_cc * B_SZ + xp_q) * 4), xp_src_base);
    if (tid >= 128 && tid < 136)
        CP_ASYNC16(pad_u32 + (unsigned)((tid - 128) * 16), paddings + (tid - 128) * 4);
    CP_COMMIT();

    float c_reg = 0.0f, m_prev = 0.0f;

#pragma unroll 1
    for (int s = 0; s < T_STEPS; s++) {
        const float* msrc = g_m[s & 1];
        const int pb = s & 1, nb = pb ^ 1;

        // ---- 4 warp-private m groups (one per mma chunk), FULL row coverage ----
#pragma unroll
        for (int j = 0; j < 4; j++) {
            const int k = j * 128 + m_row;
            CP_ASYNC16(ms_u32 + (unsigned)((k * MS + m_q) * 4),        msrc + k * B_SZ + m_q);
            CP_ASYNC16(ms_u32 + (unsigned)((k * MS + m_q + 16) * 4),   msrc + k * B_SZ + m_q + 16);
            CP_COMMIT();
        }
        // ---- xp(s+1)+pad(s+1) prefetch group ----
        if (s + 1 < T_STEPS) {
            if (tid < 128)
                CP_ASYNC16(xp_u32 + (unsigned)(((nb * 512) + xp_cc * B_SZ + xp_q) * 4),
                           xp_src_base + (size_t)(s + 1) * G_SZ * B_SZ);
            if (tid >= 128 && tid < 136)
                CP_ASYNC16(pad_u32 + (unsigned)((nb * 32 + (tid - 128) * 4) * 4),
                           paddings + (size_t)(s + 1) * B_SZ + (tid - 128) * 4);
        }
        CP_COMMIT();

        float acc1[2][2][4], acc2[2][2][4];
#pragma unroll
        for (int mt = 0; mt < 2; mt++)
#pragma unroll
            for (int nt = 0; nt < 2; nt++)
#pragma unroll
                for (int r = 0; r < 4; r++) { acc1[mt][nt][r] = 0.0f; acc2[mt][nt][r] = 0.0f; }

        // ---- mma chunks, warp-paced ----
#define MMA_CHUNK(J, WN)                                                          \
        {                                                                         \
            CP_WAIT(WN);                                                          \
            __syncwarp();                                                         \
            const int kb = (J) * 128 + w * 8 + tig;                               \
            const float* mp0 = &m_s[kb * MS];                                     \
            const float* mp4 = &m_s[(kb + 4) * MS];                               \
            _Pragma("unroll")                                                     \
            for (int mt = 0; mt < 2; mt++) {                                      \
                const int b = mt * 16 + gid;                                      \
                float x0 = mp0[b], x1 = mp0[b + 8];                               \
                float x2 = mp4[b], x3 = mp4[b + 8];                               \
                uint32_t ah0, al0, ah1, al1, ah2, al2, ah3, al3;                  \
                split_tf(x0, ah0, al0); split_tf(x1, ah1, al1);                   \
                split_tf(x2, ah2, al2); split_tf(x3, ah3, al3);                   \
                _Pragma("unroll")                                                 \
                for (int nt = 0; nt < 2; nt++) {                                  \
                    mma_tf32(acc1[mt][nt][0], acc1[mt][nt][1],                    \
                             acc1[mt][nt][2], acc1[mt][nt][3],                    \
                             ah0, ah1, ah2, ah3, Whi[J][nt][0], Whi[J][nt][1]);   \
                    mma_tf32(acc2[mt][nt][0], acc2[mt][nt][1],                    \
                             acc2[mt][nt][2], acc2[mt][nt][3],                    \
                             ah0, ah1, ah2, ah3, Wlo[J][nt][0], Wlo[J][nt][1]);   \
                    mma_tf32(acc2[mt][nt][0], acc2[mt][nt][1],                    \
                             acc2[mt][nt][2], acc2[mt][nt][3],                    \
                             al0, al1, al2, al3, Whi[J][nt][0], Whi[J][nt][1]);   \
                }                                                                 \
            }                                                                     \
        }

        MMA_CHUNK(0, 4)
        MMA_CHUNK(1, 3)
        MMA_CHUNK(2, 2)
        MMA_CHUNK(3, 1)
#undef MMA_CHUNK

        // partials -> red[w][cc][36]
        {
            float* rp = red + w * 576;
#pragma unroll
            for (int mt = 0; mt < 2; mt++)
#pragma unroll
                for (int nt = 0; nt < 2; nt++) {
                    const int b  = mt * 16 + gid;
                    const int cc = nt * 8 + tig * 2;
                    rp[cc * 36 + b]           = acc1[mt][nt][0] + acc2[mt][nt][0];
                    rp[(cc + 1) * 36 + b]     = acc1[mt][nt][1] + acc2[mt][nt][1];
                    rp[cc * 36 + b + 8]       = acc1[mt][nt][2] + acc2[mt][nt][2];
                    rp[(cc + 1) * 36 + b + 8] = acc1[mt][nt][3] + acc2[mt][nt][3];
                }
        }
        __syncthreads();

        // 16-way K reduction + xp
        {
            const int occ = tid >> 5, ob = tid & 31;
            float ssum = xp_s[pb * 512 + tid];
#pragma unroll
            for (int ww = 0; ww < 16; ww++) ssum += red[ww * 576 + occ * 36 + ob];
            gsum[tid] = ssum;
        }
        __syncthreads();

        // cell update (state in registers)
        float m2 = 0.0f, c2 = 0.0f;
        if (tid < 128) {
            float xi = gsum[(cj * 4 + 0) * 32 + cb];
            float xf = gsum[(cj * 4 + 1) * 32 + cb];
            float xg = gsum[(cj * 4 + 2) * 32 + cb];
            float xo = gsum[(cj * 4 + 3) * 32 + cb];
            float p  = pad_s[pb * 32 + cb];

            float ii = fsig(xi), ff = fsig(xf), gg = ftanh(xg), oo = fsig(xo);
            float cn = ff * c_reg + ii * gg;
            float mn = oo * ftanh(cn);
            m2 = mn + (m_prev - mn) * p;
            c2 = cn + (c_reg - cn) * p;
            c_reg = c2;
            m_prev = m2;
            g_m[(s + 1) & 1][h_o * B_SZ + cb] = m2;
        }

        // ---- grid barrier (arrive, overlap out-store, spin) ----
        __syncthreads();
        if (tid == 0) { __threadfence(); atomicAdd(&g_bar, 1); }
        if (tid < 128) {
            out[((size_t)s * B_SZ + cb) * H_SZ + h_o] = m2;
            if (write_final && s == T_STEPS - 1) {
                size_t base = (size_t)T_STEPS * B_SZ * H_SZ;
                out[base + (size_t)cb * H_SZ + h_o] = m2;
                out[base + (size_t)B_SZ * H_SZ + (size_t)cb * H_SZ + h_o] = c2;
            }
        }
        if (tid == 0) {
            int target = NBLK * (s + 1);
            while (*(volatile int*)&g_bar < target) { }
            __threadfence();
        }
        __syncthreads();
    }
}

// ---------------- launch ----------------
extern "C" void kernel_launch(void* const* d_in, const int* in_sizes, int n_in,
                              void* d_out, int out_size)
{
    const float* input = (const float*)d_in[0];
    const float* padd  = (const float*)d_in[1];
    const float* W_x   = (const float*)d_in[2];
    const float* W_h   = (const float*)d_in[3];
    const float* bias  = (const float*)d_in[4];
    float* out = (float*)d_out;

    const size_t xp_smem = (size_t)XP_SMEM_FL * sizeof(float);
    const size_t ls_smem = (size_t)SMEM_FLOATS_L * sizeof(float);
    cudaFuncSetAttribute(xproj_gemm, cudaFuncAttributeMaxDynamicSharedMemorySize, (int)xp_smem);
    cudaFuncSetAttribute(lstm_kernel, cudaFuncAttributeMaxDynamicSharedMemorySize, (int)ls_smem);

    int write_final =
        ((size_t)out_size >= (size_t)T_STEPS * B_SZ * H_SZ + 2u * B_SZ * H_SZ) ? 1 : 0;

    xproj_gemm<<<dim3(G_SZ / 128, (T_STEPS * B_SZ) / 64), 256, xp_smem>>>(input, W_x, bias);
    lstm_kernel<<<NBLK, 512, ls_smem>>>(padd, W_h, out, write_final);
}